// round 3
// baseline (speedup 1.0000x reference)
#include <cuda_runtime.h>
#include <cstdint>
#include <cstddef>

// Butterfly: B=8192 rows, N=4096, 12 stages, increasing stride.
// Persistent kernel (148 CTAs), 512 threads, tile = 12 rows (6 float2-packed
// row pairs) in 192KB smem. 4 register phases of 3 stages each, in-place.
// Raw rows staged via cp.async; next tile prefetched into freed pair slots
// during phase 3 so DRAM overlaps FFMA work. Twiddles cached in registers
// per phase and reused across all pairs (48 regs).

namespace {
constexpr int kN         = 4096;
constexpr int kBatch     = 8192;
constexpr int kThreads   = 512;
constexpr int kPairs     = 6;
constexpr int kTileRows  = 12;
constexpr int kTiles     = 683;            // 682 full + 1 tail (4 pairs)
constexpr int kGrid      = 148;            // persistent, 1 CTA/SM
constexpr int kRowBytes  = kN * 4;         // 16 KB
constexpr int kPairBytes = 2 * kRowBytes;  // 32 KB
constexpr int kSmem      = kPairs * kPairBytes;  // 196608 B
}

// float2-granule swizzle for the working (row-pair) layout. Conflict-free for
// patterns i = base + s*m, s in {1,8,64,512} (verified per half-warp).
__device__ __forceinline__ int swz(int i) {
    return (i & ~15) | ((i & 15) ^ ((i >> 4) & 7) ^ ((i >> 3) & 8));
}
// 16B-chunk swizzle for raw staging: conflict-free for consecutive-chunk
// stores (cp.async) and the 2t/2t+1 chunk reads of phase 0.
__device__ __forceinline__ int swzr(int j) { return j ^ ((j >> 3) & 1); }

__device__ __forceinline__ void cp16(uint32_t dst, const void* src) {
    asm volatile("cp.async.cg.shared.global [%0], [%1], 16;" :: "r"(dst), "l"(src));
}
__device__ __forceinline__ void cp_commit() {
    asm volatile("cp.async.commit_group;");
}
__device__ __forceinline__ void cp_wait_all() {
    asm volatile("cp.async.wait_group 0;");
}

// Stage one row pair (rows rowA, rowA+1; contiguous 32KB in gmem) into the
// pair slot at shared address sbase. 2048 16B chunks over 512 threads.
__device__ __forceinline__ void prefetch_pair(uint32_t sbase,
                                              const float* __restrict__ x,
                                              int rowA, int t) {
    const char* gb = reinterpret_cast<const char*>(x) + (size_t)rowA * kRowBytes;
    #pragma unroll
    for (int k = 0; k < 4; ++k) {
        const int j     = t + 512 * k;   // 0..2047
        const int local = j & 1023;      // chunk within row
        const int r     = j >> 10;       // 0 = rowA, 1 = rowA+1
        cp16(sbase + r * kRowBytes + 16 * swzr(local),
             gb + (size_t)r * kRowBytes + (size_t)16 * local);
    }
}

// One 2x2 butterfly applied to two rows packed in float2 lanes.
__device__ __forceinline__ void bfly(float2& x0, float2& x1, const float4 tm) {
    float2 y0, y1;
    y0.x = __fmaf_rn(tm.y, x1.x, tm.x * x0.x);
    y0.y = __fmaf_rn(tm.y, x1.y, tm.x * x0.y);
    y1.x = __fmaf_rn(tm.w, x1.x, tm.z * x0.x);
    y1.y = __fmaf_rn(tm.w, x1.y, tm.z * x0.y);
    x0 = y0;
    x1 = y1;
}

// Three in-register substages over 8 owned elements (local strides 1,2,4).
__device__ __forceinline__ void substages(float2 v[8], const float4 twr[3][4]) {
    bfly(v[0], v[1], twr[0][0]); bfly(v[2], v[3], twr[0][1]);
    bfly(v[4], v[5], twr[0][2]); bfly(v[6], v[7], twr[0][3]);
    bfly(v[0], v[2], twr[1][0]); bfly(v[1], v[3], twr[1][1]);
    bfly(v[4], v[6], twr[1][2]); bfly(v[5], v[7], twr[1][3]);
    bfly(v[0], v[4], twr[2][0]); bfly(v[1], v[5], twr[2][1]);
    bfly(v[2], v[6], twr[2][2]); bfly(v[3], v[7], twr[2][3]);
}

template <int NP>
__device__ __forceinline__ void tile_body(const float* __restrict__ x,
                                          float* __restrict__ out,
                                          const float4* __restrict__ tw4,
                                          char* sm, uint32_t smu,
                                          int row0, int nrow0, int np_next) {
    const int t = threadIdx.x;

    // ---------- Phase 0: raw -> regs -> 3 stages -> barrier -> float2 layout
    {
        float4 twr[3][4];
        #pragma unroll
        for (int u = 0; u < 3; ++u)
            #pragma unroll
            for (int pm = 0; pm < 4; ++pm)
                twr[u][pm] = tw4[u * 2048 + 4 * t + pm];

        const int ra0 = 16 * swzr(2 * t);
        const int ra1 = 16 * swzr(2 * t + 1);
        int offw[8];
        #pragma unroll
        for (int m = 0; m < 8; ++m) offw[m] = swz(8 * t + m);

        #pragma unroll 1
        for (int p = 0; p < NP; p += 2) {
            float2 v0[8], v1[8];
            {
                const char* s0 = sm + p * kPairBytes;
                const float4 a0 = *(const float4*)(s0 + ra0);
                const float4 a1 = *(const float4*)(s0 + ra1);
                const float4 b0 = *(const float4*)(s0 + kRowBytes + ra0);
                const float4 b1 = *(const float4*)(s0 + kRowBytes + ra1);
                v0[0] = make_float2(a0.x, b0.x); v0[1] = make_float2(a0.y, b0.y);
                v0[2] = make_float2(a0.z, b0.z); v0[3] = make_float2(a0.w, b0.w);
                v0[4] = make_float2(a1.x, b1.x); v0[5] = make_float2(a1.y, b1.y);
                v0[6] = make_float2(a1.z, b1.z); v0[7] = make_float2(a1.w, b1.w);
            }
            {
                const char* s1 = sm + (p + 1) * kPairBytes;
                const float4 a0 = *(const float4*)(s1 + ra0);
                const float4 a1 = *(const float4*)(s1 + ra1);
                const float4 b0 = *(const float4*)(s1 + kRowBytes + ra0);
                const float4 b1 = *(const float4*)(s1 + kRowBytes + ra1);
                v1[0] = make_float2(a0.x, b0.x); v1[1] = make_float2(a0.y, b0.y);
                v1[2] = make_float2(a0.z, b0.z); v1[3] = make_float2(a0.w, b0.w);
                v1[4] = make_float2(a1.x, b1.x); v1[5] = make_float2(a1.y, b1.y);
                v1[6] = make_float2(a1.z, b1.z); v1[7] = make_float2(a1.w, b1.w);
            }
            substages(v0, twr);
            substages(v1, twr);
            __syncthreads();   // all raw reads of pairs p,p+1 done before overwrite
            float2* B0 = (float2*)(sm + p * kPairBytes);
            float2* B1 = (float2*)(sm + (p + 1) * kPairBytes);
            #pragma unroll
            for (int m = 0; m < 8; ++m) { B0[offw[m]] = v0[m]; B1[offw[m]] = v1[m]; }
        }
    }
    __syncthreads();

    // ---------- Phases 1,2: in-place (per-thread ownership), 1 barrier each
    #pragma unroll
    for (int ph = 1; ph <= 2; ++ph) {
        const int ls = 3 * ph;          // 3 or 6
        const int s  = 1 << ls;         // 8 or 64
        const int b  = t >> ls;
        const int c  = t & (s - 1);

        float4 twr[3][4];
        #pragma unroll
        for (int u = 0; u < 3; ++u)
            #pragma unroll
            for (int pm = 0; pm < 4; ++pm)
                twr[u][pm] = tw4[(3 * ph + u) * 2048 + s * (4 * b + pm) + c];
        int off[8];
        #pragma unroll
        for (int m = 0; m < 8; ++m) off[m] = swz(b * 8 * s + c + s * m);

        #pragma unroll 1
        for (int p = 0; p < NP; p += 2) {
            float2* B0 = (float2*)(sm + p * kPairBytes);
            float2* B1 = (float2*)(sm + (p + 1) * kPairBytes);
            float2 v0[8], v1[8];
            #pragma unroll
            for (int m = 0; m < 8; ++m) { v0[m] = B0[off[m]]; v1[m] = B1[off[m]]; }
            substages(v0, twr);
            substages(v1, twr);
            #pragma unroll
            for (int m = 0; m < 8; ++m) { B0[off[m]] = v0[m]; B1[off[m]] = v1[m]; }
        }
        __syncthreads();
    }

    // ---------- Phase 3: read -> prefetch next tile into freed slots -> STG
    {
        const int s = 512;
        float4 twr[3][4];
        #pragma unroll
        for (int u = 0; u < 3; ++u)
            #pragma unroll
            for (int pm = 0; pm < 4; ++pm)
                twr[u][pm] = tw4[(9 + u) * 2048 + s * pm + t];
        int off[8];
        #pragma unroll
        for (int m = 0; m < 8; ++m) off[m] = swz(t + s * m);

        #pragma unroll 1
        for (int p = 0; p < NP; p += 2) {
            float2* B0 = (float2*)(sm + p * kPairBytes);
            float2* B1 = (float2*)(sm + (p + 1) * kPairBytes);
            float2 v0[8], v1[8];
            #pragma unroll
            for (int m = 0; m < 8; ++m) { v0[m] = B0[off[m]]; v1[m] = B1[off[m]]; }
            __syncthreads();   // every thread done reading pairs p,p+1
            if (nrow0 >= 0) {
                if (p < np_next)
                    prefetch_pair(smu + p * kPairBytes, x, nrow0 + 2 * p, t);
                if (p + 1 < np_next)
                    prefetch_pair(smu + (p + 1) * kPairBytes, x, nrow0 + 2 * p + 2, t);
            }
            cp_commit();

            substages(v0, twr);
            substages(v1, twr);

            float* o0 = out + (size_t)(row0 + 2 * p) * kN;
            float* o1 = o0 + kN;
            float* o2 = o1 + kN;
            float* o3 = o2 + kN;
            #pragma unroll
            for (int m = 0; m < 8; ++m) {
                o0[t + s * m] = v0[m].x;   // warp-contiguous 4B stores
                o1[t + s * m] = v0[m].y;
                o2[t + s * m] = v1[m].x;
                o3[t + s * m] = v1[m].y;
            }
        }
    }
}

__global__ void __launch_bounds__(kThreads, 1)
butterfly_kernel(const float* __restrict__ x,
                 const float* __restrict__ tw,
                 float* __restrict__ out) {
    extern __shared__ char sm[];
    const uint32_t smu = (uint32_t)__cvta_generic_to_shared(sm);
    const float4* tw4  = reinterpret_cast<const float4*>(tw);
    const int t = threadIdx.x;

    // Prologue: stage this CTA's first tile (always 6 full pairs).
    {
        const int row0 = blockIdx.x * kTileRows;
        #pragma unroll
        for (int p = 0; p < kPairs; ++p)
            prefetch_pair(smu + p * kPairBytes, x, row0 + 2 * p, t);
        cp_commit();
    }

    for (int tile = blockIdx.x; tile < kTiles; tile += kGrid) {
        const int row0    = tile * kTileRows;
        const int np      = min(kPairs, (kBatch - row0) >> 1);   // 6 or 4
        const int ntile   = tile + kGrid;
        const int nrow0   = (ntile < kTiles) ? ntile * kTileRows : -1;
        const int np_next = (nrow0 >= 0) ? min(kPairs, (kBatch - nrow0) >> 1) : 0;

        cp_wait_all();       // this tile's raw data resident
        __syncthreads();     // visible to all threads

        if (np == kPairs)
            tile_body<6>(x, out, tw4, sm, smu, row0, nrow0, np_next);
        else
            tile_body<4>(x, out, tw4, sm, smu, row0, nrow0, np_next);
    }
}

extern "C" void kernel_launch(void* const* d_in, const int* in_sizes, int n_in,
                              void* d_out, int out_size) {
    const float* x  = (const float*)d_in[0];   // (8192, 4096) fp32
    const float* tw = (const float*)d_in[1];   // (1,1,12,2048,2,2) fp32
    float* out      = (float*)d_out;           // (8192, 4096) fp32

    cudaFuncSetAttribute(butterfly_kernel,
                         cudaFuncAttributeMaxDynamicSharedMemorySize, kSmem);
    butterfly_kernel<<<kGrid, kThreads, kSmem>>>(x, tw, out);
}

// round 4
// speedup vs baseline: 1.0338x; 1.0338x over previous
#include <cuda_runtime.h>
#include <cstdint>
#include <cstddef>

// Butterfly transform: B=8192 rows, N=4096, 12 stages, increasing stride.
// R4: R2 structure (683 CTAs, 512 thr, 12 rows/CTA, 192KB smem, 4 register
// phases, 3 barriers/tile) + packed f32x2 math: the two float2 lanes are two
// rows sharing one twiddle, so each butterfly is 4 mul/fma.f32x2 ops instead
// of 8 FFMA. Twiddle lanes duplicated via mov.b64 on the fly, amortized over
// the two row-pairs in flight (movs go to the idle ALU pipe).

namespace {
constexpr int kN       = 4096;
constexpr int kBatch   = 8192;
constexpr int kThreads = 512;
constexpr int kRows    = 12;
constexpr int kPairs   = kRows / 2;                         // 6
constexpr int kGrid    = 683;                               // 682 full + 1 tail(4)
constexpr int kSmem    = kPairs * kN * (int)sizeof(float2); // 196608 B
}

using u64 = unsigned long long;

// float2-granule swizzle; conflict-free for i = base + s*m, s in {1,8,64,512}.
__device__ __forceinline__ int swz(int i) {
    return (i & ~15) | ((i & 15) ^ ((i >> 4) & 7) ^ ((i >> 3) & 8));
}

__device__ __forceinline__ u64 bcast2(float a) {
    u64 r; asm("mov.b64 %0, {%1, %1};" : "=l"(r) : "f"(a)); return r;
}
__device__ __forceinline__ u64 pack2(float lo, float hi) {
    u64 r; asm("mov.b64 %0, {%1, %2};" : "=l"(r) : "f"(lo), "f"(hi)); return r;
}
__device__ __forceinline__ void unpack2(u64 v, float& lo, float& hi) {
    asm("mov.b64 {%0, %1}, %2;" : "=f"(lo), "=f"(hi) : "l"(v));
}
__device__ __forceinline__ u64 mul2(u64 a, u64 b) {
    u64 d; asm("mul.rn.f32x2 %0, %1, %2;" : "=l"(d) : "l"(a), "l"(b)); return d;
}
__device__ __forceinline__ u64 fma2(u64 a, u64 b, u64 c) {
    u64 d; asm("fma.rn.f32x2 %0, %1, %2, %3;" : "=l"(d) : "l"(a), "l"(b), "l"(c));
    return d;
}

// One 2x2 butterfly applied jointly to two packed row-pairs (amortizes the
// 4 twiddle broadcast movs over both).
__device__ __forceinline__ void bfly2(u64& a0, u64& a1, u64& b0, u64& b1,
                                      const float4 tm) {
    const u64 t00 = bcast2(tm.x), t01 = bcast2(tm.y);
    const u64 t10 = bcast2(tm.z), t11 = bcast2(tm.w);
    const u64 ya0 = fma2(t01, a1, mul2(t00, a0));
    const u64 yb0 = fma2(t01, b1, mul2(t00, b0));
    const u64 ya1 = fma2(t11, a1, mul2(t10, a0));
    const u64 yb1 = fma2(t11, b1, mul2(t10, b0));
    a0 = ya0; a1 = ya1; b0 = yb0; b1 = yb1;
}

// Three in-register substages over 8 owned elements of TWO row-pairs.
__device__ __forceinline__ void substages2(u64 va[8], u64 vb[8],
                                           const float4 twr[3][4]) {
    bfly2(va[0], va[1], vb[0], vb[1], twr[0][0]);
    bfly2(va[2], va[3], vb[2], vb[3], twr[0][1]);
    bfly2(va[4], va[5], vb[4], vb[5], twr[0][2]);
    bfly2(va[6], va[7], vb[6], vb[7], twr[0][3]);

    bfly2(va[0], va[2], vb[0], vb[2], twr[1][0]);
    bfly2(va[1], va[3], vb[1], vb[3], twr[1][1]);
    bfly2(va[4], va[6], vb[4], vb[6], twr[1][2]);
    bfly2(va[5], va[7], vb[5], vb[7], twr[1][3]);

    bfly2(va[0], va[4], vb[0], vb[4], twr[2][0]);
    bfly2(va[1], va[5], vb[1], vb[5], twr[2][1]);
    bfly2(va[2], va[6], vb[2], vb[6], twr[2][2]);
    bfly2(va[3], va[7], vb[3], vb[7], twr[2][3]);
}

template <int NPAIRS>
__device__ __forceinline__ void bf_body(const float* __restrict__ x,
                                        const float* __restrict__ tw,
                                        float* __restrict__ out,
                                        int row0, u64* buf) {
    static_assert(NPAIRS % 2 == 0, "pairs processed two at a time");
    const int t = threadIdx.x;
    const float4* tw4 = reinterpret_cast<const float4*>(tw);

    // ---------------- Phase 0: stages 0..2 (strides 1,2,4) ----------------
    {
        float4 twr[3][4];
        #pragma unroll
        for (int u = 0; u < 3; ++u)
            #pragma unroll
            for (int pm = 0; pm < 4; ++pm)
                twr[u][pm] = tw4[u * 2048 + 4 * t + pm];
        int off[8];
        #pragma unroll
        for (int m = 0; m < 8; ++m) off[m] = swz(8 * t + m);

        #pragma unroll
        for (int p = 0; p < NPAIRS; p += 2) {
            u64 va[8], vb[8];
            #pragma unroll
            for (int g = 0; g < 2; ++g) {
                const float4* xa = reinterpret_cast<const float4*>(
                    x + (size_t)(row0 + 2 * (p + g)) * kN);
                const float4* xb = reinterpret_cast<const float4*>(
                    x + (size_t)(row0 + 2 * (p + g) + 1) * kN);
                const float4 a0 = xa[2 * t], a1 = xa[2 * t + 1];
                const float4 b0 = xb[2 * t], b1 = xb[2 * t + 1];
                u64* v = g ? vb : va;
                v[0] = pack2(a0.x, b0.x); v[1] = pack2(a0.y, b0.y);
                v[2] = pack2(a0.z, b0.z); v[3] = pack2(a0.w, b0.w);
                v[4] = pack2(a1.x, b1.x); v[5] = pack2(a1.y, b1.y);
                v[6] = pack2(a1.z, b1.z); v[7] = pack2(a1.w, b1.w);
            }

            substages2(va, vb, twr);

            u64* Ba = buf + p * kN;
            u64* Bb = Ba + kN;
            #pragma unroll
            for (int m = 0; m < 8; ++m) { Ba[off[m]] = va[m]; Bb[off[m]] = vb[m]; }
        }
    }
    __syncthreads();

    // ------------- Phases 1,2: stages 3..8 (strides 8..256), smem ---------
    #pragma unroll
    for (int ph = 1; ph <= 2; ++ph) {
        const int ls = 3 * ph;          // 3 or 6
        const int s  = 1 << ls;         // 8 or 64
        const int b  = t >> ls;
        const int c  = t & (s - 1);

        float4 twr[3][4];
        #pragma unroll
        for (int u = 0; u < 3; ++u)
            #pragma unroll
            for (int pm = 0; pm < 4; ++pm)
                twr[u][pm] = tw4[(3 * ph + u) * 2048 + s * (4 * b + pm) + c];
        int off[8];
        #pragma unroll
        for (int m = 0; m < 8; ++m) off[m] = swz(b * 8 * s + c + s * m);

        #pragma unroll
        for (int p = 0; p < NPAIRS; p += 2) {
            u64* Ba = buf + p * kN;
            u64* Bb = Ba + kN;
            u64 va[8], vb[8];
            #pragma unroll
            for (int m = 0; m < 8; ++m) { va[m] = Ba[off[m]]; vb[m] = Bb[off[m]]; }

            substages2(va, vb, twr);

            #pragma unroll
            for (int m = 0; m < 8; ++m) { Ba[off[m]] = va[m]; Bb[off[m]] = vb[m]; }
        }
        __syncthreads();
    }

    // ------------- Phase 3: stages 9..11 (strides 512..2048) -> out -------
    {
        const int s = 512;  // b = 0, c = t
        float4 twr[3][4];
        #pragma unroll
        for (int u = 0; u < 3; ++u)
            #pragma unroll
            for (int pm = 0; pm < 4; ++pm)
                twr[u][pm] = tw4[(9 + u) * 2048 + s * pm + t];
        int off[8];
        #pragma unroll
        for (int m = 0; m < 8; ++m) off[m] = swz(t + s * m);

        #pragma unroll
        for (int p = 0; p < NPAIRS; p += 2) {
            u64* Ba = buf + p * kN;
            u64* Bb = Ba + kN;
            u64 va[8], vb[8];
            #pragma unroll
            for (int m = 0; m < 8; ++m) { va[m] = Ba[off[m]]; vb[m] = Bb[off[m]]; }

            substages2(va, vb, twr);

            float* o0 = out + (size_t)(row0 + 2 * p) * kN;
            float* o1 = o0 + kN;
            float* o2 = o1 + kN;
            float* o3 = o2 + kN;
            #pragma unroll
            for (int m = 0; m < 8; ++m) {
                float lo, hi;
                unpack2(va[m], lo, hi);
                o0[t + s * m] = lo;       // warp-contiguous 4B stores
                o1[t + s * m] = hi;
                unpack2(vb[m], lo, hi);
                o2[t + s * m] = lo;
                o3[t + s * m] = hi;
            }
        }
    }
}

__global__ void __launch_bounds__(kThreads, 1)
butterfly_kernel(const float* __restrict__ x,
                 const float* __restrict__ tw,
                 float* __restrict__ out) {
    extern __shared__ u64 buf[];
    const int row0 = blockIdx.x * kRows;
    if (blockIdx.x < kGrid - 1) {
        bf_body<6>(x, tw, out, row0, buf);   // rows 0..8183
    } else {
        bf_body<4>(x, tw, out, row0, buf);   // rows 8184..8191
    }
}

extern "C" void kernel_launch(void* const* d_in, const int* in_sizes, int n_in,
                              void* d_out, int out_size) {
    const float* x  = (const float*)d_in[0];   // (8192, 4096) fp32
    const float* tw = (const float*)d_in[1];   // (1,1,12,2048,2,2) fp32
    float* out      = (float*)d_out;           // (8192, 4096) fp32

    cudaFuncSetAttribute(butterfly_kernel,
                         cudaFuncAttributeMaxDynamicSharedMemorySize, kSmem);
    butterfly_kernel<<<kGrid, kThreads, kSmem>>>(x, tw, out);
}